// round 14
// baseline (speedup 1.0000x reference)
#include <cuda_runtime.h>
#include <cuda_bf16.h>

// MatrixFactorization: out[r] = dot(concat(Wd[dow],Wt[time],Wm[month],Wdy[day]), W_item[dest])
// N=1048576, NUM_FACTOR=128, NUM_DIM=32.
//
// R14 = R10 (best: warp-per-row float4 loads, 2 software-pipelined 8-row
// batches, merged 16-shuffle reduction, vectorized index loads) +
// __launch_bounds__(128,10): reg cap 51 (>= measured demand 47, no spill),
// 10 blocks/SM = 40 resident warps (vs 36) to fill L1tex idle cycles.
// R13's LDG.64 split reverted: wavefronts = lines touched, splitting loads
// only added instructions.

#define WARPS_PER_BLOCK 4
#define THREADS (WARPS_PER_BLOCK * 32)
#define BATCH 8
#define ROWS_PER_WARP 16   // 2 pipelined batches of 8

struct Idx8 { int si[BATCH]; int di[BATCH]; };

__device__ __forceinline__ void load_idx(const int* __restrict__ idx_arr,
                                         const int* __restrict__ dest,
                                         int rb, Idx8& o)
{
    const int4 ia = *reinterpret_cast<const int4*>(idx_arr + rb);
    const int4 ib = *reinterpret_cast<const int4*>(idx_arr + rb + 4);
    const int4 da = *reinterpret_cast<const int4*>(dest + rb);
    const int4 db = *reinterpret_cast<const int4*>(dest + rb + 4);
    o.si[0] = ia.x; o.si[1] = ia.y; o.si[2] = ia.z; o.si[3] = ia.w;
    o.si[4] = ib.x; o.si[5] = ib.y; o.si[6] = ib.z; o.si[7] = ib.w;
    o.di[0] = da.x; o.di[1] = da.y; o.di[2] = da.z; o.di[3] = da.w;
    o.di[4] = db.x; o.di[5] = db.y; o.di[6] = db.z; o.di[7] = db.w;
}

__device__ __forceinline__ void load_data(const float* __restrict__ Wsub,
                                          const float* __restrict__ Witem,
                                          const Idx8& ix, int off, int lane,
                                          float4* u, float4* v)
{
#pragma unroll
    for (int i = 0; i < BATCH; i++)
        v[i] = *reinterpret_cast<const float4*>(Witem + (ix.di[i] * 128 + lane * 4));
#pragma unroll
    for (int i = 0; i < BATCH; i++)
        u[i] = *reinterpret_cast<const float4*>(Wsub + (ix.si[i] * 32 + off));
}

__device__ __forceinline__ void reduce_store(const float4* u, const float4* v,
                                             float* __restrict__ out, int rb,
                                             int lane, int rowid, bool is_writer)
{
    float s[BATCH];
#pragma unroll
    for (int i = 0; i < BATCH; i++) {
        float acc = u[i].x * v[i].x;
        acc = fmaf(u[i].y, v[i].y, acc);
        acc = fmaf(u[i].z, v[i].z, acc);
        acc = fmaf(u[i].w, v[i].w, acc);
        s[i] = acc;
    }
#pragma unroll
    for (int i = 0; i < BATCH; i++)
        s[i] += __shfl_xor_sync(0xFFFFFFFFu, s[i], 16);
    float t[4];
#pragma unroll
    for (int i = 0; i < 4; i++)
        t[i] = (lane < 16) ? s[2 * i] : s[2 * i + 1];
#pragma unroll
    for (int i = 0; i < 4; i++)
        t[i] += __shfl_xor_sync(0xFFFFFFFFu, t[i], 8);
    float q[2];
#pragma unroll
    for (int i = 0; i < 2; i++)
        q[i] = ((lane & 8) == 0) ? t[2 * i] : t[2 * i + 1];
#pragma unroll
    for (int i = 0; i < 2; i++)
        q[i] += __shfl_xor_sync(0xFFFFFFFFu, q[i], 4);
    float z = ((lane & 4) == 0) ? q[0] : q[1];
    z += __shfl_xor_sync(0xFFFFFFFFu, z, 2);
    z += __shfl_xor_sync(0xFFFFFFFFu, z, 1);

    if (is_writer) out[rb + rowid] = z;
}

__global__ __launch_bounds__(THREADS, 10)
void mf_kernel(const int* __restrict__ dow,
               const int* __restrict__ tim,
               const int* __restrict__ mon,
               const int* __restrict__ day,
               const int* __restrict__ dest,
               const float* __restrict__ Wdow,
               const float* __restrict__ Wtim,
               const float* __restrict__ Wmon,
               const float* __restrict__ Wday,
               const float* __restrict__ Witem,
               float* __restrict__ out,
               int n)
{
    const int warp_id = blockIdx.x * WARPS_PER_BLOCK + (threadIdx.x >> 5);
    const int lane = threadIdx.x & 31;
    const int sub = lane >> 3;
    const int off = (lane & 7) * 4;

    const float* __restrict__ Wsub =
        (sub == 0) ? Wdow : (sub == 1) ? Wtim : (sub == 2) ? Wmon : Wday;
    const int* __restrict__ idx_arr =
        (sub == 0) ? dow : (sub == 1) ? tim : (sub == 2) ? mon : day;

    const int rowid = ((lane >> 4) & 1) | (((lane >> 3) & 1) << 1) | (((lane >> 2) & 1) << 2);
    const bool is_writer = ((lane & 3) == 0);

    const int base = warp_id * ROWS_PER_WARP;
    if (base >= n) return;
    const int rb0 = base;
    const int rb1 = base + BATCH;

    // ---- Pipelined schedule ----
    Idx8 ix0, ix1;
    float4 u0[BATCH], v0[BATCH];
    float4 u1[BATCH], v1[BATCH];

    load_idx(idx_arr, dest, rb0, ix0);               // idx0
    load_data(Wsub, Witem, ix0, off, lane, u0, v0);  // data0 (16 loads in flight)
    load_idx(idx_arr, dest, rb1, ix1);               // idx1 overlaps data0 flight

    reduce_store(u0, v0, out, rb0, lane, rowid, is_writer);  // epilogue0

    load_data(Wsub, Witem, ix1, off, lane, u1, v1);  // data1: idx1 already resident
    reduce_store(u1, v1, out, rb1, lane, rowid, is_writer);  // epilogue1
}

extern "C" void kernel_launch(void* const* d_in, const int* in_sizes, int n_in,
                              void* d_out, int out_size)
{
    const int*   dow   = (const int*)d_in[0];
    const int*   tim   = (const int*)d_in[1];
    const int*   mon   = (const int*)d_in[2];
    const int*   day   = (const int*)d_in[3];
    const int*   dest  = (const int*)d_in[4];
    const float* Wdow  = (const float*)d_in[5];
    const float* Wtim  = (const float*)d_in[6];
    const float* Wmon  = (const float*)d_in[7];
    const float* Wday  = (const float*)d_in[8];
    const float* Witem = (const float*)d_in[9];
    float* out = (float*)d_out;

    const int n = in_sizes[0];
    const int rows_per_block = WARPS_PER_BLOCK * ROWS_PER_WARP;  // 64
    const int grid = (n + rows_per_block - 1) / rows_per_block;

    mf_kernel<<<grid, THREADS>>>(dow, tim, mon, day, dest,
                                 Wdow, Wtim, Wmon, Wday, Witem, out, n);
}

// round 15
// speedup vs baseline: 1.6905x; 1.6905x over previous
#include <cuda_runtime.h>
#include <cuda_bf16.h>

// MatrixFactorization: out[r] = dot(concat(Wd[dow],Wt[time],Wm[month],Wdy[day]), W_item[dest])
// N=1048576, NUM_FACTOR=128, NUM_DIM=32.
//
// R15 = R10 (best @53.7us: warp-per-row float4 loads, 2 software-pipelined
// 8-row batches, merged 16-shuffle reduction, vectorized index loads, NATURAL
// register allocation -- min-blocks launch_bounds hints cause spills, proven
// R11/R14) with one scheduling change: batch0's FMA dot (dot8) runs BEFORE
// data1's loads are issued, and batch0's shuffle tree (reduce8) runs AFTER,
// so data1's ~250cyc L2 flight overlaps the ~100cyc shuffle tree.

#define WARPS_PER_BLOCK 4
#define THREADS (WARPS_PER_BLOCK * 32)
#define BATCH 8
#define ROWS_PER_WARP 16   // 2 pipelined batches of 8

struct Idx8 { int si[BATCH]; int di[BATCH]; };

__device__ __forceinline__ void load_idx(const int* __restrict__ idx_arr,
                                         const int* __restrict__ dest,
                                         int rb, Idx8& o)
{
    const int4 ia = *reinterpret_cast<const int4*>(idx_arr + rb);
    const int4 ib = *reinterpret_cast<const int4*>(idx_arr + rb + 4);
    const int4 da = *reinterpret_cast<const int4*>(dest + rb);
    const int4 db = *reinterpret_cast<const int4*>(dest + rb + 4);
    o.si[0] = ia.x; o.si[1] = ia.y; o.si[2] = ia.z; o.si[3] = ia.w;
    o.si[4] = ib.x; o.si[5] = ib.y; o.si[6] = ib.z; o.si[7] = ib.w;
    o.di[0] = da.x; o.di[1] = da.y; o.di[2] = da.z; o.di[3] = da.w;
    o.di[4] = db.x; o.di[5] = db.y; o.di[6] = db.z; o.di[7] = db.w;
}

__device__ __forceinline__ void load_data(const float* __restrict__ Wsub,
                                          const float* __restrict__ Witem,
                                          const Idx8& ix, int off, int lane,
                                          float4* u, float4* v)
{
#pragma unroll
    for (int i = 0; i < BATCH; i++)
        v[i] = *reinterpret_cast<const float4*>(Witem + (ix.di[i] * 128 + lane * 4));
#pragma unroll
    for (int i = 0; i < BATCH; i++)
        u[i] = *reinterpret_cast<const float4*>(Wsub + (ix.si[i] * 32 + off));
}

// FMA consumption only: waits on the data loads, frees u/v registers.
__device__ __forceinline__ void dot8(const float4* u, const float4* v, float* s)
{
#pragma unroll
    for (int i = 0; i < BATCH; i++) {
        float acc = u[i].x * v[i].x;
        acc = fmaf(u[i].y, v[i].y, acc);
        acc = fmaf(u[i].z, v[i].z, acc);
        acc = fmaf(u[i].w, v[i].w, acc);
        s[i] = acc;
    }
}

// Shuffle tree + store only: no dependence on the next batch's loads.
__device__ __forceinline__ void reduce8(float* s, float* __restrict__ out, int rb,
                                        int lane, int rowid, bool is_writer)
{
#pragma unroll
    for (int i = 0; i < BATCH; i++)
        s[i] += __shfl_xor_sync(0xFFFFFFFFu, s[i], 16);
    float t[4];
#pragma unroll
    for (int i = 0; i < 4; i++)
        t[i] = (lane < 16) ? s[2 * i] : s[2 * i + 1];
#pragma unroll
    for (int i = 0; i < 4; i++)
        t[i] += __shfl_xor_sync(0xFFFFFFFFu, t[i], 8);
    float q[2];
#pragma unroll
    for (int i = 0; i < 2; i++)
        q[i] = ((lane & 8) == 0) ? t[2 * i] : t[2 * i + 1];
#pragma unroll
    for (int i = 0; i < 2; i++)
        q[i] += __shfl_xor_sync(0xFFFFFFFFu, q[i], 4);
    float z = ((lane & 4) == 0) ? q[0] : q[1];
    z += __shfl_xor_sync(0xFFFFFFFFu, z, 2);
    z += __shfl_xor_sync(0xFFFFFFFFu, z, 1);

    if (is_writer) out[rb + rowid] = z;
}

__global__ __launch_bounds__(THREADS)   // natural regs — NO min-blocks hint
void mf_kernel(const int* __restrict__ dow,
               const int* __restrict__ tim,
               const int* __restrict__ mon,
               const int* __restrict__ day,
               const int* __restrict__ dest,
               const float* __restrict__ Wdow,
               const float* __restrict__ Wtim,
               const float* __restrict__ Wmon,
               const float* __restrict__ Wday,
               const float* __restrict__ Witem,
               float* __restrict__ out,
               int n)
{
    const int warp_id = blockIdx.x * WARPS_PER_BLOCK + (threadIdx.x >> 5);
    const int lane = threadIdx.x & 31;
    const int sub = lane >> 3;
    const int off = (lane & 7) * 4;

    const float* __restrict__ Wsub =
        (sub == 0) ? Wdow : (sub == 1) ? Wtim : (sub == 2) ? Wmon : Wday;
    const int* __restrict__ idx_arr =
        (sub == 0) ? dow : (sub == 1) ? tim : (sub == 2) ? mon : day;

    const int rowid = ((lane >> 4) & 1) | (((lane >> 3) & 1) << 1) | (((lane >> 2) & 1) << 2);
    const bool is_writer = ((lane & 3) == 0);

    const int base = warp_id * ROWS_PER_WARP;
    if (base >= n) return;
    const int rb0 = base;
    const int rb1 = base + BATCH;

    Idx8 ix0, ix1;
    float4 u0[BATCH], v0[BATCH];
    float4 u1[BATCH], v1[BATCH];
    float s0[BATCH], s1[BATCH];

    load_idx(idx_arr, dest, rb0, ix0);               // idx0
    load_data(Wsub, Witem, ix0, off, lane, u0, v0);  // data0 (16 loads in flight)
    load_idx(idx_arr, dest, rb1, ix1);               // idx1 overlaps data0 flight

    dot8(u0, v0, s0);                                // consume data0, free u0/v0

    load_data(Wsub, Witem, ix1, off, lane, u1, v1);  // data1 issues BEFORE tree0

    reduce8(s0, out, rb0, lane, rowid, is_writer);   // tree0 overlaps data1 flight

    dot8(u1, v1, s1);
    reduce8(s1, out, rb1, lane, rowid, is_writer);
}

extern "C" void kernel_launch(void* const* d_in, const int* in_sizes, int n_in,
                              void* d_out, int out_size)
{
    const int*   dow   = (const int*)d_in[0];
    const int*   tim   = (const int*)d_in[1];
    const int*   mon   = (const int*)d_in[2];
    const int*   day   = (const int*)d_in[3];
    const int*   dest  = (const int*)d_in[4];
    const float* Wdow  = (const float*)d_in[5];
    const float* Wtim  = (const float*)d_in[6];
    const float* Wmon  = (const float*)d_in[7];
    const float* Wday  = (const float*)d_in[8];
    const float* Witem = (const float*)d_in[9];
    float* out = (float*)d_out;

    const int n = in_sizes[0];
    const int rows_per_block = WARPS_PER_BLOCK * ROWS_PER_WARP;  // 64
    const int grid = (n + rows_per_block - 1) / rows_per_block;

    mf_kernel<<<grid, THREADS>>>(dow, tim, mon, day, dest,
                                 Wdow, Wtim, Wmon, Wday, Witem, out, n);
}

// round 16
// speedup vs baseline: 1.8089x; 1.0701x over previous
#include <cuda_runtime.h>
#include <cuda_bf16.h>

// MatrixFactorization: out[r] = dot(concat(Wd[dow],Wt[time],Wm[month],Wdy[day]), W_item[dest])
// N=1048576, NUM_FACTOR=128, NUM_DIM=32.
//
// R16 = R15's split dot/reduce pipeline extended to 4 rotating batches/warp,
// NATURAL register allocation (min-blocks hints spill: R11/R14).
// Per batch b:  dot8(b) [frees u/v regs] -> load_data(b+1) -> load_idx(b+2)
//               -> reduce8(b) [overlaps data(b+1) flight].
// Peak live set identical to R15 (one u/v set + one Idx8 in flight), so no
// spill pressure, but prologue/epilogue amortized over 4 batches not 2.

#define WARPS_PER_BLOCK 4
#define THREADS (WARPS_PER_BLOCK * 32)
#define BATCH 8
#define NBATCH 4
#define ROWS_PER_WARP (BATCH * NBATCH)   // 32

struct Idx8 { int si[BATCH]; int di[BATCH]; };

__device__ __forceinline__ void load_idx(const int* __restrict__ idx_arr,
                                         const int* __restrict__ dest,
                                         int rb, Idx8& o)
{
    const int4 ia = *reinterpret_cast<const int4*>(idx_arr + rb);
    const int4 ib = *reinterpret_cast<const int4*>(idx_arr + rb + 4);
    const int4 da = *reinterpret_cast<const int4*>(dest + rb);
    const int4 db = *reinterpret_cast<const int4*>(dest + rb + 4);
    o.si[0] = ia.x; o.si[1] = ia.y; o.si[2] = ia.z; o.si[3] = ia.w;
    o.si[4] = ib.x; o.si[5] = ib.y; o.si[6] = ib.z; o.si[7] = ib.w;
    o.di[0] = da.x; o.di[1] = da.y; o.di[2] = da.z; o.di[3] = da.w;
    o.di[4] = db.x; o.di[5] = db.y; o.di[6] = db.z; o.di[7] = db.w;
}

__device__ __forceinline__ void load_data(const float* __restrict__ Wsub,
                                          const float* __restrict__ Witem,
                                          const Idx8& ix, int off, int lane,
                                          float4* u, float4* v)
{
#pragma unroll
    for (int i = 0; i < BATCH; i++)
        v[i] = *reinterpret_cast<const float4*>(Witem + (ix.di[i] * 128 + lane * 4));
#pragma unroll
    for (int i = 0; i < BATCH; i++)
        u[i] = *reinterpret_cast<const float4*>(Wsub + (ix.si[i] * 32 + off));
}

// FMA consumption only: waits on the data loads, frees u/v registers.
__device__ __forceinline__ void dot8(const float4* u, const float4* v, float* s)
{
#pragma unroll
    for (int i = 0; i < BATCH; i++) {
        float acc = u[i].x * v[i].x;
        acc = fmaf(u[i].y, v[i].y, acc);
        acc = fmaf(u[i].z, v[i].z, acc);
        acc = fmaf(u[i].w, v[i].w, acc);
        s[i] = acc;
    }
}

// Shuffle tree + store only: no dependence on the next batch's loads.
__device__ __forceinline__ void reduce8(float* s, float* __restrict__ out, int rb,
                                        int lane, int rowid, bool is_writer)
{
#pragma unroll
    for (int i = 0; i < BATCH; i++)
        s[i] += __shfl_xor_sync(0xFFFFFFFFu, s[i], 16);
    float t[4];
#pragma unroll
    for (int i = 0; i < 4; i++)
        t[i] = (lane < 16) ? s[2 * i] : s[2 * i + 1];
#pragma unroll
    for (int i = 0; i < 4; i++)
        t[i] += __shfl_xor_sync(0xFFFFFFFFu, t[i], 8);
    float q[2];
#pragma unroll
    for (int i = 0; i < 2; i++)
        q[i] = ((lane & 8) == 0) ? t[2 * i] : t[2 * i + 1];
#pragma unroll
    for (int i = 0; i < 2; i++)
        q[i] += __shfl_xor_sync(0xFFFFFFFFu, q[i], 4);
    float z = ((lane & 4) == 0) ? q[0] : q[1];
    z += __shfl_xor_sync(0xFFFFFFFFu, z, 2);
    z += __shfl_xor_sync(0xFFFFFFFFu, z, 1);

    if (is_writer) out[rb + rowid] = z;
}

__global__ __launch_bounds__(THREADS)   // natural regs — NO min-blocks hint
void mf_kernel(const int* __restrict__ dow,
               const int* __restrict__ tim,
               const int* __restrict__ mon,
               const int* __restrict__ day,
               const int* __restrict__ dest,
               const float* __restrict__ Wdow,
               const float* __restrict__ Wtim,
               const float* __restrict__ Wmon,
               const float* __restrict__ Wday,
               const float* __restrict__ Witem,
               float* __restrict__ out,
               int n)
{
    const int warp_id = blockIdx.x * WARPS_PER_BLOCK + (threadIdx.x >> 5);
    const int lane = threadIdx.x & 31;
    const int sub = lane >> 3;
    const int off = (lane & 7) * 4;

    const float* __restrict__ Wsub =
        (sub == 0) ? Wdow : (sub == 1) ? Wtim : (sub == 2) ? Wmon : Wday;
    const int* __restrict__ idx_arr =
        (sub == 0) ? dow : (sub == 1) ? tim : (sub == 2) ? mon : day;

    const int rowid = ((lane >> 4) & 1) | (((lane >> 3) & 1) << 1) | (((lane >> 2) & 1) << 2);
    const bool is_writer = ((lane & 3) == 0);

    const int base = warp_id * ROWS_PER_WARP;
    if (base >= n) return;

    Idx8 ix_cur, ix_next;
    float4 u[BATCH], v[BATCH];
    float s[BATCH];

    load_idx(idx_arr, dest, base, ix_cur);                 // idx0
    load_data(Wsub, Witem, ix_cur, off, lane, u, v);       // data0 in flight
    load_idx(idx_arr, dest, base + BATCH, ix_next);        // idx1 overlaps data0

#pragma unroll
    for (int b = 0; b < NBATCH; b++) {
        const int rb = base + b * BATCH;

        dot8(u, v, s);                                     // consume data(b), free u/v

        if (b + 1 < NBATCH) {
            ix_cur = ix_next;
            load_data(Wsub, Witem, ix_cur, off, lane, u, v);   // data(b+1) in flight
            if (b + 2 < NBATCH)
                load_idx(idx_arr, dest, rb + 2 * BATCH, ix_next);  // idx(b+2)
        }

        reduce8(s, out, rb, lane, rowid, is_writer);       // tree(b) overlaps flight
    }
}

extern "C" void kernel_launch(void* const* d_in, const int* in_sizes, int n_in,
                              void* d_out, int out_size)
{
    const int*   dow   = (const int*)d_in[0];
    const int*   tim   = (const int*)d_in[1];
    const int*   mon   = (const int*)d_in[2];
    const int*   day   = (const int*)d_in[3];
    const int*   dest  = (const int*)d_in[4];
    const float* Wdow  = (const float*)d_in[5];
    const float* Wtim  = (const float*)d_in[6];
    const float* Wmon  = (const float*)d_in[7];
    const float* Wday  = (const float*)d_in[8];
    const float* Witem = (const float*)d_in[9];
    float* out = (float*)d_out;

    const int n = in_sizes[0];
    const int rows_per_block = WARPS_PER_BLOCK * ROWS_PER_WARP;  // 128
    const int grid = (n + rows_per_block - 1) / rows_per_block;

    mf_kernel<<<grid, THREADS>>>(dow, tim, mon, day, dest,
                                 Wdow, Wtim, Wmon, Wday, Witem, out, n);
}